// round 15
// baseline (speedup 1.0000x reference)
#include <cuda_runtime.h>
#include <cuda_fp16.h>
#include <math.h>
#include <stdint.h>

// Problem constants: B=8, N=4096, C=1024, H=16, dh=64
#define BB 8
#define NN 4096
#define CC 1024
#define HH 16
#define DH 64
#define M_ROWS (BB * NN)          // 32768
#define QKV_COLS (3 * CC)         // 3072

// ---------------- static scratch -------------------------------------------
__device__ __align__(128) __half g_Yh[(size_t)M_ROWS * QKV_COLS];  // qkv fp16
__device__ __align__(128) __half g_Zh[(size_t)M_ROWS * CC];        // attn@v fp16
__device__ __align__(128) __half g_attnh[(size_t)BB * HH * DH * DH]; // attn fp16 [bh][d][e]
__device__ __align__(128) float g_sspart[(size_t)(M_ROWS / 128) * 2048];
__device__ __align__(128) float g_Sp2[(size_t)BB * HH * 2 * DH * DH]; // partial grams
__device__ __align__(128) __half g_Af16[(size_t)M_ROWS * CC];      // x fp16 [M,K]
__device__ __align__(128) __half g_Wf16[(size_t)QKV_COLS * CC];    // W^T fp16 [N,K]

// ============================ helpers =======================================
__device__ __forceinline__ uint32_t smem_u32(const void* p) {
  uint32_t a;
  asm("{ .reg .u64 t; cvta.to.shared.u64 t, %1; cvt.u32.u64 %0, t; }" : "=r"(a) : "l"(p));
  return a;
}
__device__ __forceinline__ void cp_async16(uint32_t dst, const void* src) {
  asm volatile("cp.async.cg.shared.global [%0], [%1], 16;" :: "r"(dst), "l"(src));
}
__device__ __forceinline__ void ldsm_x4(uint32_t* r, uint32_t addr) {
  asm volatile("ldmatrix.sync.aligned.m8n8.x4.shared.b16 {%0,%1,%2,%3}, [%4];"
               : "=r"(r[0]), "=r"(r[1]), "=r"(r[2]), "=r"(r[3]) : "r"(addr));
}
__device__ __forceinline__ void ldsm_x4_t(uint32_t* r, uint32_t addr) {
  asm volatile("ldmatrix.sync.aligned.m8n8.x4.trans.shared.b16 {%0,%1,%2,%3}, [%4];"
               : "=r"(r[0]), "=r"(r[1]), "=r"(r[2]), "=r"(r[3]) : "r"(addr));
}
__device__ __forceinline__ void ldsm_x2(uint32_t* r, uint32_t addr) {
  asm volatile("ldmatrix.sync.aligned.m8n8.x2.shared.b16 {%0,%1}, [%2];"
               : "=r"(r[0]), "=r"(r[1]) : "r"(addr));
}
__device__ __forceinline__ void ldsm_x2_t(uint32_t* r, uint32_t addr) {
  asm volatile("ldmatrix.sync.aligned.m8n8.x2.trans.shared.b16 {%0,%1}, [%2];"
               : "=r"(r[0]), "=r"(r[1]) : "r"(addr));
}
__device__ __forceinline__ void mma_f16(float* c, const uint32_t* a, uint32_t b0,
                                        uint32_t b1) {
  asm volatile(
      "mma.sync.aligned.m16n8k16.row.col.f32.f16.f16.f32 "
      "{%0,%1,%2,%3}, {%4,%5,%6,%7}, {%8,%9}, {%0,%1,%2,%3};"
      : "+f"(c[0]), "+f"(c[1]), "+f"(c[2]), "+f"(c[3])
      : "r"(a[0]), "r"(a[1]), "r"(a[2]), "r"(a[3]), "r"(b0), "r"(b1));
}

// ---------------------------------------------------------------------------
// fp16 tensor-core GEMM (Round-12/14 measured-best config, unchanged).
// ---------------------------------------------------------------------------
#define HSTAGE 32768                     // A 16KB + B 16KB
#define HGEMM_SMEM (3 * HSTAGE)          // 96KB

template <int OUT_HALF, int SUMSQ>
__global__ __launch_bounds__(256, 2) void hgemm(
    const __half* __restrict__ A, const __half* __restrict__ Bt,
    void* __restrict__ Cv, const float* __restrict__ bias, int N, int K) {
  extern __shared__ char smembuf[];
  const uint32_t sbase = smem_u32(smembuf);
  const int tid = threadIdx.x, lane = tid & 31, wid = tid >> 5;
  const int wm = wid & 1, wn = wid >> 1;   // 2 x 4 warp grid
  const size_t bm = (size_t)blockIdx.y * 128;
  const size_t bn = (size_t)blockIdx.x * 128;

  float acc[4][4][4];
#pragma unroll
  for (int mi = 0; mi < 4; ++mi)
#pragma unroll
    for (int nj = 0; nj < 4; ++nj)
#pragma unroll
      for (int j = 0; j < 4; ++j) acc[mi][nj][j] = 0.0f;

  auto issue_loads = [&](int kt, int st) {
    const uint32_t sA = sbase + st * HSTAGE;
    const uint32_t sB = sA + 16384;
    const __half* Ag = A + bm * K + kt * 64;
    const __half* Bg = Bt + bn * K + kt * 64;
#pragma unroll
    for (int i = 0; i < 4; ++i) {
      int idx = tid + i * 256;
      int r = idx >> 3, g = idx & 7;
      cp_async16(sA + r * 128 + ((g ^ (r & 7)) << 4), Ag + (size_t)r * K + g * 8);
    }
#pragma unroll
    for (int i = 0; i < 4; ++i) {
      int idx = tid + i * 256;
      int r = idx >> 3, g = idx & 7;
      cp_async16(sB + r * 128 + ((g ^ (r & 7)) << 4), Bg + (size_t)r * K + g * 8);
    }
    asm volatile("cp.async.commit_group;");
  };

  const int nt = K >> 6;
  issue_loads(0, 0);
  if (nt > 1) issue_loads(1, 1);

  const int hi8 = (lane >> 4) & 1;
  const int rsel = lane & 15;

  for (int kt = 0; kt < nt; ++kt) {
    if (kt + 1 < nt) {
      asm volatile("cp.async.wait_group 1;");
    } else {
      asm volatile("cp.async.wait_group 0;");
    }
    __syncthreads();
    if (kt + 2 < nt) issue_loads(kt + 2, (kt + 2) % 3);

    const int st = kt % 3;
    const uint32_t sA = sbase + st * HSTAGE;
    const uint32_t sB = sA + 16384;
#pragma unroll
    for (int ks = 0; ks < 4; ++ks) {
      const int g16 = 2 * ks + hi8;
      uint32_t a[4][4], b[2][4];
#pragma unroll
      for (int mi = 0; mi < 4; ++mi) {
        int mrow = wm * 64 + mi * 16 + rsel;
        ldsm_x4(a[mi], sA + mrow * 128 + ((g16 ^ (mrow & 7)) << 4));
      }
#pragma unroll
      for (int nb = 0; nb < 2; ++nb) {
        int nrow = wn * 32 + nb * 16 + rsel;
        ldsm_x4(b[nb], sB + nrow * 128 + ((g16 ^ (nrow & 7)) << 4));
      }
#pragma unroll
      for (int mi = 0; mi < 4; ++mi)
#pragma unroll
        for (int nj = 0; nj < 4; ++nj)
          mma_f16(acc[mi][nj], a[mi], b[nj >> 1][nj & 1], b[nj >> 1][(nj & 1) + 2]);
    }
  }

  const int rr = lane >> 2, cc2 = (lane & 3) * 2;
#pragma unroll
  for (int mi = 0; mi < 4; ++mi) {
    size_t row = bm + wm * 64 + mi * 16 + rr;
#pragma unroll
    for (int nj = 0; nj < 4; ++nj) {
      size_t col = bn + wn * 32 + nj * 8 + cc2;
      if (OUT_HALF) {
        __half* C = (__half*)Cv;
        *(__half2*)(C + row * N + col) =
            __floats2half2_rn(acc[mi][nj][0], acc[mi][nj][1]);
        *(__half2*)(C + (row + 8) * N + col) =
            __floats2half2_rn(acc[mi][nj][2], acc[mi][nj][3]);
      } else {
        float* C = (float*)Cv;
        float b0 = 0.0f, b1 = 0.0f;
        if (bias) { b0 = bias[col]; b1 = bias[col + 1]; }
        *(float2*)(C + row * N + col) =
            make_float2(acc[mi][nj][0] + b0, acc[mi][nj][1] + b1);
        *(float2*)(C + (row + 8) * N + col) =
            make_float2(acc[mi][nj][2] + b0, acc[mi][nj][3] + b1);
      }
    }
  }

  if (SUMSQ) {
    if (bn < 2048) {
      __syncthreads();
      float* sq = (float*)smembuf;          // [128 cols][16 slots]
      const int slot = wm * 8 + rr;
#pragma unroll
      for (int nj = 0; nj < 4; ++nj) {
        int c0 = wn * 32 + nj * 8 + cc2;
        float p0 = 0.0f, p1 = 0.0f;
#pragma unroll
        for (int mi = 0; mi < 4; ++mi) {
          p0 += acc[mi][nj][0] * acc[mi][nj][0] + acc[mi][nj][2] * acc[mi][nj][2];
          p1 += acc[mi][nj][1] * acc[mi][nj][1] + acc[mi][nj][3] * acc[mi][nj][3];
        }
        sq[c0 * 16 + slot] = p0;
        sq[(c0 + 1) * 16 + slot] = p1;
      }
      __syncthreads();
      if (tid < 128) {
        float s = 0.0f;
#pragma unroll
        for (int j = 0; j < 16; ++j) s += sq[tid * 16 + j];
        g_sspart[(size_t)blockIdx.y * 2048 + bn + tid] = s;
      }
    }
  }
}

// ---------------------------------------------------------------------------
__global__ __launch_bounds__(256) void f2h_kernel(const float* __restrict__ A,
                                                  __half* __restrict__ O) {
  size_t i = ((size_t)blockIdx.x * 256 + threadIdx.x) * 8;
  float4 v0 = *(const float4*)(A + i);
  float4 v1 = *(const float4*)(A + i + 4);
  union { __half2 h[4]; uint4 u; } o;
  o.h[0] = __floats2half2_rn(v0.x, v0.y);
  o.h[1] = __floats2half2_rn(v0.z, v0.w);
  o.h[2] = __floats2half2_rn(v1.x, v1.y);
  o.h[3] = __floats2half2_rn(v1.z, v1.w);
  *(uint4*)(O + i) = o.u;
}

// ---------------------------------------------------------------------------
__global__ __launch_bounds__(256) void wtrans_kernel(const float* __restrict__ W,
                                                     __half* __restrict__ O,
                                                     int K, int N) {
  __shared__ float s[32][33];
  const int n0 = blockIdx.x * 32, k0 = blockIdx.y * 32;
  const int tx = threadIdx.x & 31, tg = threadIdx.x >> 5;
#pragma unroll
  for (int j = 0; j < 4; ++j) {
    int kr = tg + j * 8;
    s[kr][tx] = W[(size_t)(k0 + kr) * N + n0 + tx];
  }
  __syncthreads();
#pragma unroll
  for (int j = 0; j < 4; ++j) {
    int nr = tg + j * 8;
    O[(size_t)(n0 + nr) * K + k0 + tx] = __float2half_rn(s[tx][nr]);
  }
}

// ---------------------------------------------------------------------------
// Partial gram per (seg, b, h): tensor-core S_seg = q k^T over 2048 tokens,
// 3-stage pipelined loads, writes fp32 partial [64][64] to g_Sp2.
// ---------------------------------------------------------------------------
#define GRSM_STAGE 32768                 // q 16KB + k 16KB
#define GRSM_SMEM (3 * GRSM_STAGE)       // 96KB

__global__ __launch_bounds__(256) void gramsm_part() {
  extern __shared__ char gsm[];
  const uint32_t sbase = smem_u32(gsm);
  const int seg = blockIdx.x;            // 0..1
  const int bh = blockIdx.y, b = bh >> 4, h = bh & 15;
  const int tid = threadIdx.x, lane = tid & 31, wid = tid >> 5;
  const __half* Yq = g_Yh + (size_t)(b * NN + seg * 2048) * QKV_COLS + h * DH;
  const __half* Yk = Yq + CC;

  float acc[4][4] = {};
  const int e0 = wid * 8;

  auto issue_chunk = [&](int ch, int st) {
    const uint32_t qb = sbase + st * GRSM_STAGE;
    const uint32_t kb = qb + 16384;
#pragma unroll
    for (int i = 0; i < 4; ++i) {
      int idx = tid + i * 256;
      int r = idx >> 3, g = idx & 7;
      size_t go = (size_t)(ch * 128 + r) * QKV_COLS + g * 8;
      uint32_t so = r * 128 + ((g ^ (r & 7)) << 4);
      cp_async16(qb + so, Yq + go);
      cp_async16(kb + so, Yk + go);
    }
    asm volatile("cp.async.commit_group;");
  };

  issue_chunk(0, 0);
  issue_chunk(1, 1);

  for (int ch = 0; ch < 16; ++ch) {
    if (ch + 1 < 16) {
      asm volatile("cp.async.wait_group 1;");
    } else {
      asm volatile("cp.async.wait_group 0;");
    }
    __syncthreads();
    if (ch + 2 < 16) issue_chunk(ch + 2, (ch + 2) % 3);

    const uint32_t qb = sbase + (ch % 3) * GRSM_STAGE;
    const uint32_t kb = qb + 16384;
#pragma unroll
    for (int s = 0; s < 8; ++s) {
      const int tokA = s * 16 + (lane & 7) + ((lane >> 4) << 3);
      uint32_t a[4][4];
#pragma unroll
      for (int mi = 0; mi < 4; ++mi) {
        int gd = mi * 2 + ((lane >> 3) & 1);
        ldsm_x4_t(a[mi], qb + tokA * 128 + ((gd ^ (tokA & 7)) << 4));
      }
      const int tokB = s * 16 + (lane & 7) + (((lane >> 3) & 1) << 3);
      uint32_t bf[2];
      ldsm_x2_t(bf, kb + tokB * 128 + ((wid ^ (tokB & 7)) << 4));
#pragma unroll
      for (int mi = 0; mi < 4; ++mi)
        mma_f16(acc[mi], a[mi], bf[0], bf[1]);
    }
  }

  float* Sout = g_Sp2 + ((size_t)bh * 2 + seg) * (DH * DH);
  const int rr = lane >> 2, cc2 = (lane & 3) * 2;
#pragma unroll
  for (int mi = 0; mi < 4; ++mi) {
    *(float2*)(Sout + (mi * 16 + rr) * 64 + e0 + cc2) =
        make_float2(acc[mi][0], acc[mi][1]);
    *(float2*)(Sout + (mi * 16 + 8 + rr) * 64 + e0 + cc2) =
        make_float2(acc[mi][2], acc[mi][3]);
  }
}

// ---------------------------------------------------------------------------
// Finalize: sum 2 partial grams, fold 1/(|q||k|)*temp (norms reduced from
// g_sspart), softmax over e, write attn fp16 [d][e].
// ---------------------------------------------------------------------------
__global__ __launch_bounds__(256) void softmax_fin(const float* __restrict__ temp) {
  __shared__ float S[64][65];
  __shared__ float nq[64], nk[64];
  const int bh = blockIdx.x, b = bh >> 4, h = bh & 15;
  const int tid = threadIdx.x;

  if (tid < 64) {
    float sq = 0.0f, sk = 0.0f;
#pragma unroll
    for (int t = 0; t < 32; ++t) {
      const float* P = g_sspart + (size_t)(b * 32 + t) * 2048;
      sq += P[h * DH + tid];
      sk += P[CC + h * DH + tid];
    }
    nq[tid] = fmaxf(sqrtf(sq), 1e-12f);
    nk[tid] = fmaxf(sqrtf(sk), 1e-12f);
  }

  const float* P0 = g_Sp2 + (size_t)bh * 2 * (DH * DH);
  const float* P1 = P0 + DH * DH;
  for (int i = tid; i < DH * DH; i += 256)
    S[i >> 6][i & 63] = P0[i] + P1[i];
  __syncthreads();

  if (tid < 64) {
    const int d = tid;
    const float sc = temp[h] / nq[d];
    float row[64];
    float m = -3.402823466e38f;
#pragma unroll
    for (int e = 0; e < 64; ++e) {
      row[e] = S[d][e] * sc / nk[e];
      m = fmaxf(m, row[e]);
    }
    float sum = 0.0f;
#pragma unroll
    for (int e = 0; e < 64; ++e) {
      row[e] = expf(row[e] - m);
      sum += row[e];
    }
    const float inv = 1.0f / sum;
    __half2* Ao = (__half2*)(g_attnh + (size_t)bh * 4096 + d * 64);
#pragma unroll
    for (int e2 = 0; e2 < 32; ++e2)
      Ao[e2] = __floats2half2_rn(row[2 * e2] * inv, row[2 * e2 + 1] * inv);
  }
}

// ---------------------------------------------------------------------------
// Tensor-core attnv: Z[n][d] = sum_e v[n][e] attn[d][e].
// ---------------------------------------------------------------------------
__global__ __launch_bounds__(256) void attnv_tc_kernel() {
  __shared__ __align__(16) __half vt[256 * 64];
  __shared__ __align__(16) __half at[64 * 64];
  const int bh = blockIdx.y, b = bh >> 4, h = bh & 15;
  const int tb = blockIdx.x * 256;
  const int tid = threadIdx.x, lane = tid & 31, wid = tid >> 5;
  const int wm = wid & 3, wd = wid >> 2;
  const uint32_t vb = smem_u32(vt), ab = smem_u32(at);

  const __half* Vg = g_Yh + (size_t)(b * NN + tb) * QKV_COLS + 2 * CC + h * DH;
#pragma unroll
  for (int i = 0; i < 8; ++i) {
    int idx = tid + i * 256;
    int r = idx >> 3, g = idx & 7;
    cp_async16(vb + r * 128 + ((g ^ (r & 7)) << 4), Vg + (size_t)r * QKV_COLS + g * 8);
  }
  const __half* Ag = g_attnh + (size_t)bh * 4096;
#pragma unroll
  for (int i = 0; i < 2; ++i) {
    int idx = tid + i * 256;
    int r = idx >> 3, g = idx & 7;
    cp_async16(ab + r * 128 + ((g ^ (r & 7)) << 4), Ag + r * 64 + g * 8);
  }
  asm volatile("cp.async.commit_group;");
  asm volatile("cp.async.wait_group 0;");
  __syncthreads();

  float acc[4][4][4] = {};
#pragma unroll
  for (int ks = 0; ks < 4; ++ks) {
    const int ge0 = ks * 2;
    uint32_t a[4][4], bf[4][2];
#pragma unroll
    for (int mi = 0; mi < 4; ++mi) {
      int tok = wm * 64 + mi * 16 + (lane & 7) + (((lane >> 3) & 1) << 3);
      int gg = ge0 + (lane >> 4);
      ldsm_x4(a[mi], vb + tok * 128 + ((gg ^ (tok & 7)) << 4));
    }
#pragma unroll
    for (int dj = 0; dj < 4; ++dj) {
      int d = wd * 32 + dj * 8 + (lane & 7);
      int gg = ge0 + ((lane >> 3) & 1);
      ldsm_x2(bf[dj], ab + d * 128 + ((gg ^ (d & 7)) << 4));
    }
#pragma unroll
    for (int mi = 0; mi < 4; ++mi)
#pragma unroll
      for (int dj = 0; dj < 4; ++dj)
        mma_f16(acc[mi][dj], a[mi], bf[dj][0], bf[dj][1]);
  }

  const int rr = lane >> 2, cc2 = (lane & 3) * 2;
#pragma unroll
  for (int mi = 0; mi < 4; ++mi) {
    size_t tok = (size_t)(b * NN + tb + wm * 64 + mi * 16 + rr);
#pragma unroll
    for (int dj = 0; dj < 4; ++dj) {
      size_t col = h * DH + wd * 32 + dj * 8 + cc2;
      *(__half2*)(g_Zh + tok * CC + col) =
          __floats2half2_rn(acc[mi][dj][0], acc[mi][dj][1]);
      *(__half2*)(g_Zh + (tok + 8) * CC + col) =
          __floats2half2_rn(acc[mi][dj][2], acc[mi][dj][3]);
    }
  }
}

// ---------------------------------------------------------------------------
extern "C" void kernel_launch(void* const* d_in, const int* in_sizes, int n_in,
                              void* d_out, int out_size) {
  const float* x      = (const float*)d_in[0];
  const float* w_qkv  = (const float*)d_in[1];
  const float* temp   = (const float*)d_in[2];
  const float* w_proj = (const float*)d_in[3];
  const float* b_proj = (const float*)d_in[4];
  float* out = (float*)d_out;

  static __half *Yh = nullptr, *Ah = nullptr, *Wh = nullptr, *Zh = nullptr;
  if (Yh == nullptr) {
    cudaGetSymbolAddress((void**)&Yh, g_Yh);
    cudaGetSymbolAddress((void**)&Zh, g_Zh);
    cudaGetSymbolAddress((void**)&Ah, g_Af16);
    cudaGetSymbolAddress((void**)&Wh, g_Wf16);
    cudaFuncSetAttribute((const void*)hgemm<1, 1>,
                         cudaFuncAttributeMaxDynamicSharedMemorySize, HGEMM_SMEM);
    cudaFuncSetAttribute((const void*)hgemm<0, 0>,
                         cudaFuncAttributeMaxDynamicSharedMemorySize, HGEMM_SMEM);
    cudaFuncSetAttribute((const void*)gramsm_part,
                         cudaFuncAttributeMaxDynamicSharedMemorySize, GRSM_SMEM);
  }

  // prep
  f2h_kernel<<<(size_t)M_ROWS * CC / 2048, 256>>>(x, Ah);
  wtrans_kernel<<<dim3(QKV_COLS / 32, CC / 32), 256>>>(w_qkv, Wh, CC, QKV_COLS);

  // K1: qkv = x @ w_qkv -> fp16 Yh, + sumsq partials
  hgemm<1, 1><<<dim3(QKV_COLS / 128, M_ROWS / 128), 256, HGEMM_SMEM>>>(
      Ah, Wh, Yh, nullptr, QKV_COLS, CC);

  // gram (2 token segments) + softmax finalize
  gramsm_part<<<dim3(2, BB * HH), 256, GRSM_SMEM>>>();
  softmax_fin<<<BB * HH, 256>>>(temp);

  attnv_tc_kernel<<<dim3(NN / 256, BB * HH), 256>>>();

  // K5
  wtrans_kernel<<<dim3(CC / 32, CC / 32), 256>>>(w_proj, Wh, CC, CC);
  hgemm<0, 0><<<dim3(CC / 128, M_ROWS / 128), 256, HGEMM_SMEM>>>(
      Zh, Wh, out, b_proj, CC, CC);
}

// round 16
// speedup vs baseline: 1.0435x; 1.0435x over previous
#include <cuda_runtime.h>
#include <cuda_fp16.h>
#include <math.h>
#include <stdint.h>

// Problem constants: B=8, N=4096, C=1024, H=16, dh=64
#define BB 8
#define NN 4096
#define CC 1024
#define HH 16
#define DH 64
#define M_ROWS (BB * NN)          // 32768
#define QKV_COLS (3 * CC)         // 3072

// ---------------- static scratch -------------------------------------------
__device__ __align__(128) __half g_Yh[(size_t)M_ROWS * QKV_COLS];  // qkv fp16
__device__ __align__(128) __half g_Zh[(size_t)M_ROWS * CC];        // attn@v fp16
__device__ __align__(128) __half g_attnh[(size_t)BB * HH * DH * DH]; // attn fp16 [bh][d][e]
__device__ __align__(128) float g_sspart[(size_t)(M_ROWS / 128) * 2048];
__device__ __align__(128) __half g_Af16[(size_t)M_ROWS * CC];      // x fp16 [M,K]
__device__ __align__(128) __half g_Wf16[(size_t)QKV_COLS * CC];    // W^T fp16 [N,K]

// ============================ helpers =======================================
__device__ __forceinline__ uint32_t smem_u32(const void* p) {
  uint32_t a;
  asm("{ .reg .u64 t; cvta.to.shared.u64 t, %1; cvt.u32.u64 %0, t; }" : "=r"(a) : "l"(p));
  return a;
}
__device__ __forceinline__ void cp_async16(uint32_t dst, const void* src) {
  asm volatile("cp.async.cg.shared.global [%0], [%1], 16;" :: "r"(dst), "l"(src));
}
__device__ __forceinline__ void ldsm_x4(uint32_t* r, uint32_t addr) {
  asm volatile("ldmatrix.sync.aligned.m8n8.x4.shared.b16 {%0,%1,%2,%3}, [%4];"
               : "=r"(r[0]), "=r"(r[1]), "=r"(r[2]), "=r"(r[3]) : "r"(addr));
}
__device__ __forceinline__ void ldsm_x4_t(uint32_t* r, uint32_t addr) {
  asm volatile("ldmatrix.sync.aligned.m8n8.x4.trans.shared.b16 {%0,%1,%2,%3}, [%4];"
               : "=r"(r[0]), "=r"(r[1]), "=r"(r[2]), "=r"(r[3]) : "r"(addr));
}
__device__ __forceinline__ void ldsm_x2(uint32_t* r, uint32_t addr) {
  asm volatile("ldmatrix.sync.aligned.m8n8.x2.shared.b16 {%0,%1}, [%2];"
               : "=r"(r[0]), "=r"(r[1]) : "r"(addr));
}
__device__ __forceinline__ void ldsm_x2_t(uint32_t* r, uint32_t addr) {
  asm volatile("ldmatrix.sync.aligned.m8n8.x2.trans.shared.b16 {%0,%1}, [%2];"
               : "=r"(r[0]), "=r"(r[1]) : "r"(addr));
}
__device__ __forceinline__ void mma_f16(float* c, const uint32_t* a, uint32_t b0,
                                        uint32_t b1) {
  asm volatile(
      "mma.sync.aligned.m16n8k16.row.col.f32.f16.f16.f32 "
      "{%0,%1,%2,%3}, {%4,%5,%6,%7}, {%8,%9}, {%0,%1,%2,%3};"
      : "+f"(c[0]), "+f"(c[1]), "+f"(c[2]), "+f"(c[3])
      : "r"(a[0]), "r"(a[1]), "r"(a[2]), "r"(a[3]), "r"(b0), "r"(b1));
}

// ---------------------------------------------------------------------------
// fp16 tensor-core GEMM: C[M,N] = A[M,K] @ W[N,K]^T. CTA tile 128x128,
// 256 threads (8 warps: 2(M) x 4(N)), warp tile 64x32, BK=64, 3-stage
// cp.async pipeline, 96KB smem -> 2 CTAs/SM. (Measured-best config.)
// OUT_HALF: fp16 out. SUMSQ: per-(Mtile,col) sumsq partials for cols<2048.
// ---------------------------------------------------------------------------
#define HSTAGE 32768                     // A 16KB + B 16KB
#define HGEMM_SMEM (3 * HSTAGE)          // 96KB

template <int OUT_HALF, int SUMSQ>
__global__ __launch_bounds__(256, 2) void hgemm(
    const __half* __restrict__ A, const __half* __restrict__ Bt,
    void* __restrict__ Cv, const float* __restrict__ bias, int N, int K) {
  extern __shared__ char smembuf[];
  const uint32_t sbase = smem_u32(smembuf);
  const int tid = threadIdx.x, lane = tid & 31, wid = tid >> 5;
  const int wm = wid & 1, wn = wid >> 1;   // 2 x 4 warp grid
  const size_t bm = (size_t)blockIdx.y * 128;
  const size_t bn = (size_t)blockIdx.x * 128;

  float acc[4][4][4];
#pragma unroll
  for (int mi = 0; mi < 4; ++mi)
#pragma unroll
    for (int nj = 0; nj < 4; ++nj)
#pragma unroll
      for (int j = 0; j < 4; ++j) acc[mi][nj][j] = 0.0f;

  auto issue_loads = [&](int kt, int st) {
    const uint32_t sA = sbase + st * HSTAGE;
    const uint32_t sB = sA + 16384;
    const __half* Ag = A + bm * K + kt * 64;
    const __half* Bg = Bt + bn * K + kt * 64;
#pragma unroll
    for (int i = 0; i < 4; ++i) {          // A: 1024 granules
      int idx = tid + i * 256;
      int r = idx >> 3, g = idx & 7;
      cp_async16(sA + r * 128 + ((g ^ (r & 7)) << 4), Ag + (size_t)r * K + g * 8);
    }
#pragma unroll
    for (int i = 0; i < 4; ++i) {          // B: 1024 granules
      int idx = tid + i * 256;
      int r = idx >> 3, g = idx & 7;
      cp_async16(sB + r * 128 + ((g ^ (r & 7)) << 4), Bg + (size_t)r * K + g * 8);
    }
    asm volatile("cp.async.commit_group;");
  };

  const int nt = K >> 6;
  issue_loads(0, 0);
  if (nt > 1) issue_loads(1, 1);

  const int hi8 = (lane >> 4) & 1;
  const int rsel = lane & 15;

  for (int kt = 0; kt < nt; ++kt) {
    if (kt + 1 < nt) {
      asm volatile("cp.async.wait_group 1;");
    } else {
      asm volatile("cp.async.wait_group 0;");
    }
    __syncthreads();
    if (kt + 2 < nt) issue_loads(kt + 2, (kt + 2) % 3);

    const int st = kt % 3;
    const uint32_t sA = sbase + st * HSTAGE;
    const uint32_t sB = sA + 16384;
#pragma unroll
    for (int ks = 0; ks < 4; ++ks) {
      const int g16 = 2 * ks + hi8;
      uint32_t a[4][4], b[2][4];
#pragma unroll
      for (int mi = 0; mi < 4; ++mi) {
        int mrow = wm * 64 + mi * 16 + rsel;
        ldsm_x4(a[mi], sA + mrow * 128 + ((g16 ^ (mrow & 7)) << 4));
      }
#pragma unroll
      for (int nb = 0; nb < 2; ++nb) {
        int nrow = wn * 32 + nb * 16 + rsel;
        ldsm_x4(b[nb], sB + nrow * 128 + ((g16 ^ (nrow & 7)) << 4));
      }
#pragma unroll
      for (int mi = 0; mi < 4; ++mi)
#pragma unroll
        for (int nj = 0; nj < 4; ++nj)
          mma_f16(acc[mi][nj], a[mi], b[nj >> 1][nj & 1], b[nj >> 1][(nj & 1) + 2]);
    }
  }

  const int rr = lane >> 2, cc2 = (lane & 3) * 2;
#pragma unroll
  for (int mi = 0; mi < 4; ++mi) {
    size_t row = bm + wm * 64 + mi * 16 + rr;
#pragma unroll
    for (int nj = 0; nj < 4; ++nj) {
      size_t col = bn + wn * 32 + nj * 8 + cc2;
      if (OUT_HALF) {
        __half* C = (__half*)Cv;
        *(__half2*)(C + row * N + col) =
            __floats2half2_rn(acc[mi][nj][0], acc[mi][nj][1]);
        *(__half2*)(C + (row + 8) * N + col) =
            __floats2half2_rn(acc[mi][nj][2], acc[mi][nj][3]);
      } else {
        float* C = (float*)Cv;
        float b0 = 0.0f, b1 = 0.0f;
        if (bias) { b0 = bias[col]; b1 = bias[col + 1]; }
        *(float2*)(C + row * N + col) =
            make_float2(acc[mi][nj][0] + b0, acc[mi][nj][1] + b1);
        *(float2*)(C + (row + 8) * N + col) =
            make_float2(acc[mi][nj][2] + b0, acc[mi][nj][3] + b1);
      }
    }
  }

  if (SUMSQ) {
    if (bn < 2048) {
      __syncthreads();
      float* sq = (float*)smembuf;          // [128 cols][16 slots] = 8KB
      const int slot = wm * 8 + rr;
#pragma unroll
      for (int nj = 0; nj < 4; ++nj) {
        int c0 = wn * 32 + nj * 8 + cc2;
        float p0 = 0.0f, p1 = 0.0f;
#pragma unroll
        for (int mi = 0; mi < 4; ++mi) {
          p0 += acc[mi][nj][0] * acc[mi][nj][0] + acc[mi][nj][2] * acc[mi][nj][2];
          p1 += acc[mi][nj][1] * acc[mi][nj][1] + acc[mi][nj][3] * acc[mi][nj][3];
        }
        sq[c0 * 16 + slot] = p0;
        sq[(c0 + 1) * 16 + slot] = p1;
      }
      __syncthreads();
      if (tid < 128) {
        float s = 0.0f;
#pragma unroll
        for (int j = 0; j < 16; ++j) s += sq[tid * 16 + j];
        g_sspart[(size_t)blockIdx.y * 2048 + bn + tid] = s;
      }
    }
  }
}

// ---------------------------------------------------------------------------
__global__ __launch_bounds__(256) void f2h_kernel(const float* __restrict__ A,
                                                  __half* __restrict__ O) {
  size_t i = ((size_t)blockIdx.x * 256 + threadIdx.x) * 8;
  float4 v0 = *(const float4*)(A + i);
  float4 v1 = *(const float4*)(A + i + 4);
  union { __half2 h[4]; uint4 u; } o;
  o.h[0] = __floats2half2_rn(v0.x, v0.y);
  o.h[1] = __floats2half2_rn(v0.z, v0.w);
  o.h[2] = __floats2half2_rn(v1.x, v1.y);
  o.h[3] = __floats2half2_rn(v1.z, v1.w);
  *(uint4*)(O + i) = o.u;
}

// ---------------------------------------------------------------------------
__global__ __launch_bounds__(256) void wtrans_kernel(const float* __restrict__ W,
                                                     __half* __restrict__ O,
                                                     int K, int N) {
  __shared__ float s[32][33];
  const int n0 = blockIdx.x * 32, k0 = blockIdx.y * 32;
  const int tx = threadIdx.x & 31, tg = threadIdx.x >> 5;
#pragma unroll
  for (int j = 0; j < 4; ++j) {
    int kr = tg + j * 8;
    s[kr][tx] = W[(size_t)(k0 + kr) * N + n0 + tx];
  }
  __syncthreads();
#pragma unroll
  for (int j = 0; j < 4; ++j) {
    int nr = tg + j * 8;
    O[(size_t)(n0 + nr) * K + k0 + tx] = __float2half_rn(s[tx][nr]);
  }
}

// ---------------------------------------------------------------------------
// Fused gram + softmax per (b,h), 3-stage pipelined loads. Norms reduced
// directly from g_sspart (no separate reduce kernel).
// ---------------------------------------------------------------------------
#define GRSM_STAGE 32768                 // q 16KB + k 16KB
#define GRSM_SMEM (3 * GRSM_STAGE)       // 96KB; S (64x68 fp32) overlays after

__global__ __launch_bounds__(256) void gramsm_kernel(const float* __restrict__ temp) {
  extern __shared__ char gsm[];
  __shared__ float nq[64], nk[64];
  const uint32_t sbase = smem_u32(gsm);
  const int bh = blockIdx.x, b = bh >> 4, h = bh & 15;
  const int tid = threadIdx.x, lane = tid & 31, wid = tid >> 5;
  const __half* Yq = g_Yh + (size_t)b * NN * QKV_COLS + h * DH;
  const __half* Yk = Yq + CC;

  float acc[4][4] = {};
  const int e0 = wid * 8;

  auto issue_chunk = [&](int ch, int st) {
    const uint32_t qb = sbase + st * GRSM_STAGE;
    const uint32_t kb = qb + 16384;
#pragma unroll
    for (int i = 0; i < 4; ++i) {
      int idx = tid + i * 256;
      int r = idx >> 3, g = idx & 7;
      size_t go = (size_t)(ch * 128 + r) * QKV_COLS + g * 8;
      uint32_t so = r * 128 + ((g ^ (r & 7)) << 4);
      cp_async16(qb + so, Yq + go);
      cp_async16(kb + so, Yk + go);
    }
    asm volatile("cp.async.commit_group;");
  };

  issue_chunk(0, 0);
  issue_chunk(1, 1);

  // norms: reduce 32 per-Mtile partials for this (b,h)'s 64+64 cols
  if (tid < 64) {
    float sq = 0.0f, sk = 0.0f;
#pragma unroll
    for (int t = 0; t < 32; ++t) {
      const float* P = g_sspart + (size_t)(b * 32 + t) * 2048;
      sq += P[h * DH + tid];
      sk += P[CC + h * DH + tid];
    }
    nq[tid] = fmaxf(sqrtf(sq), 1e-12f);
    nk[tid] = fmaxf(sqrtf(sk), 1e-12f);
  }

  for (int ch = 0; ch < 32; ++ch) {
    if (ch + 1 < 32) {
      asm volatile("cp.async.wait_group 1;");
    } else {
      asm volatile("cp.async.wait_group 0;");
    }
    __syncthreads();
    if (ch + 2 < 32) issue_chunk(ch + 2, (ch + 2) % 3);

    const uint32_t qb = sbase + (ch % 3) * GRSM_STAGE;
    const uint32_t kb = qb + 16384;
#pragma unroll
    for (int s = 0; s < 8; ++s) {
      const int tokA = s * 16 + (lane & 7) + ((lane >> 4) << 3);
      uint32_t a[4][4];
#pragma unroll
      for (int mi = 0; mi < 4; ++mi) {
        int gd = mi * 2 + ((lane >> 3) & 1);
        ldsm_x4_t(a[mi], qb + tokA * 128 + ((gd ^ (tokA & 7)) << 4));
      }
      const int tokB = s * 16 + (lane & 7) + (((lane >> 3) & 1) << 3);
      uint32_t bf[2];
      ldsm_x2_t(bf, kb + tokB * 128 + ((wid ^ (tokB & 7)) << 4));
#pragma unroll
      for (int mi = 0; mi < 4; ++mi)
        mma_f16(acc[mi], a[mi], bf[0], bf[1]);
    }
  }
  __syncthreads();

  float* S = (float*)gsm;      // [64][68]
  const int rr = lane >> 2, cc2 = (lane & 3) * 2;
#pragma unroll
  for (int mi = 0; mi < 4; ++mi) {
    S[(mi * 16 + rr) * 68 + e0 + cc2]     = acc[mi][0];
    S[(mi * 16 + rr) * 68 + e0 + cc2 + 1] = acc[mi][1];
    S[(mi * 16 + 8 + rr) * 68 + e0 + cc2]     = acc[mi][2];
    S[(mi * 16 + 8 + rr) * 68 + e0 + cc2 + 1] = acc[mi][3];
  }
  __syncthreads();

  if (tid < 64) {
    const int d = tid;
    const float sc = temp[h] / nq[d];
    float row[64];
    float m = -3.402823466e38f;
#pragma unroll
    for (int e = 0; e < 64; ++e) {
      row[e] = S[d * 68 + e] * sc / nk[e];
      m = fmaxf(m, row[e]);
    }
    float sum = 0.0f;
#pragma unroll
    for (int e = 0; e < 64; ++e) {
      row[e] = expf(row[e] - m);
      sum += row[e];
    }
    const float inv = 1.0f / sum;
    __half2* Ao = (__half2*)(g_attnh + (size_t)bh * 4096 + d * 64);
#pragma unroll
    for (int e2 = 0; e2 < 32; ++e2)
      Ao[e2] = __floats2half2_rn(row[2 * e2] * inv, row[2 * e2 + 1] * inv);
  }
}

// ---------------------------------------------------------------------------
// Tensor-core attnv: Z[n][d] = sum_e v[n][e] attn[d][e].
// ---------------------------------------------------------------------------
__global__ __launch_bounds__(256) void attnv_tc_kernel() {
  __shared__ __align__(16) __half vt[256 * 64];
  __shared__ __align__(16) __half at[64 * 64];
  const int bh = blockIdx.y, b = bh >> 4, h = bh & 15;
  const int tb = blockIdx.x * 256;
  const int tid = threadIdx.x, lane = tid & 31, wid = tid >> 5;
  const int wm = wid & 3, wd = wid >> 2;
  const uint32_t vb = smem_u32(vt), ab = smem_u32(at);

  const __half* Vg = g_Yh + (size_t)(b * NN + tb) * QKV_COLS + 2 * CC + h * DH;
#pragma unroll
  for (int i = 0; i < 8; ++i) {
    int idx = tid + i * 256;
    int r = idx >> 3, g = idx & 7;
    cp_async16(vb + r * 128 + ((g ^ (r & 7)) << 4), Vg + (size_t)r * QKV_COLS + g * 8);
  }
  const __half* Ag = g_attnh + (size_t)bh * 4096;
#pragma unroll
  for (int i = 0; i < 2; ++i) {
    int idx = tid + i * 256;
    int r = idx >> 3, g = idx & 7;
    cp_async16(ab + r * 128 + ((g ^ (r & 7)) << 4), Ag + r * 64 + g * 8);
  }
  asm volatile("cp.async.commit_group;");
  asm volatile("cp.async.wait_group 0;");
  __syncthreads();

  float acc[4][4][4] = {};
#pragma unroll
  for (int ks = 0; ks < 4; ++ks) {
    const int ge0 = ks * 2;
    uint32_t a[4][4], bf[4][2];
#pragma unroll
    for (int mi = 0; mi < 4; ++mi) {
      int tok = wm * 64 + mi * 16 + (lane & 7) + (((lane >> 3) & 1) << 3);
      int gg = ge0 + (lane >> 4);
      ldsm_x4(a[mi], vb + tok * 128 + ((gg ^ (tok & 7)) << 4));
    }
#pragma unroll
    for (int dj = 0; dj < 4; ++dj) {
      int d = wd * 32 + dj * 8 + (lane & 7);
      int gg = ge0 + ((lane >> 3) & 1);
      ldsm_x2(bf[dj], ab + d * 128 + ((gg ^ (d & 7)) << 4));
    }
#pragma unroll
    for (int mi = 0; mi < 4; ++mi)
#pragma unroll
      for (int dj = 0; dj < 4; ++dj)
        mma_f16(acc[mi][dj], a[mi], bf[dj][0], bf[dj][1]);
  }

  const int rr = lane >> 2, cc2 = (lane & 3) * 2;
#pragma unroll
  for (int mi = 0; mi < 4; ++mi) {
    size_t tok = (size_t)(b * NN + tb + wm * 64 + mi * 16 + rr);
#pragma unroll
    for (int dj = 0; dj < 4; ++dj) {
      size_t col = h * DH + wd * 32 + dj * 8 + cc2;
      *(__half2*)(g_Zh + tok * CC + col) =
          __floats2half2_rn(acc[mi][dj][0], acc[mi][dj][1]);
      *(__half2*)(g_Zh + (tok + 8) * CC + col) =
          __floats2half2_rn(acc[mi][dj][2], acc[mi][dj][3]);
    }
  }
}

// ---------------------------------------------------------------------------
extern "C" void kernel_launch(void* const* d_in, const int* in_sizes, int n_in,
                              void* d_out, int out_size) {
  const float* x      = (const float*)d_in[0];
  const float* w_qkv  = (const float*)d_in[1];
  const float* temp   = (const float*)d_in[2];
  const float* w_proj = (const float*)d_in[3];
  const float* b_proj = (const float*)d_in[4];
  float* out = (float*)d_out;

  static __half *Yh = nullptr, *Ah = nullptr, *Wh = nullptr, *Zh = nullptr;
  if (Yh == nullptr) {
    cudaGetSymbolAddress((void**)&Yh, g_Yh);
    cudaGetSymbolAddress((void**)&Zh, g_Zh);
    cudaGetSymbolAddress((void**)&Ah, g_Af16);
    cudaGetSymbolAddress((void**)&Wh, g_Wf16);
    cudaFuncSetAttribute((const void*)hgemm<1, 1>,
                         cudaFuncAttributeMaxDynamicSharedMemorySize, HGEMM_SMEM);
    cudaFuncSetAttribute((const void*)hgemm<0, 0>,
                         cudaFuncAttributeMaxDynamicSharedMemorySize, HGEMM_SMEM);
    cudaFuncSetAttribute((const void*)gramsm_kernel,
                         cudaFuncAttributeMaxDynamicSharedMemorySize, GRSM_SMEM);
  }

  // prep
  f2h_kernel<<<(size_t)M_ROWS * CC / 2048, 256>>>(x, Ah);
  wtrans_kernel<<<dim3(QKV_COLS / 32, CC / 32), 256>>>(w_qkv, Wh, CC, QKV_COLS);

  // K1: qkv = x @ w_qkv -> fp16 Yh, + sumsq partials
  hgemm<1, 1><<<dim3(QKV_COLS / 128, M_ROWS / 128), 256, HGEMM_SMEM>>>(
      Ah, Wh, Yh, nullptr, QKV_COLS, CC);

  gramsm_kernel<<<BB * HH, 256, GRSM_SMEM>>>(temp);
  attnv_tc_kernel<<<dim3(NN / 256, BB * HH), 256>>>();

  // K5
  wtrans_kernel<<<dim3(CC / 32, CC / 32), 256>>>(w_proj, Wh, CC, CC);
  hgemm<0, 0><<<dim3(CC / 128, M_ROWS / 128), 256, HGEMM_SMEM>>>(
      Zh, Wh, out, b_proj, CC, CC);
}

// round 17
// speedup vs baseline: 1.0439x; 1.0004x over previous
#include <cuda_runtime.h>
#include <cuda_fp16.h>
#include <math.h>
#include <stdint.h>

// Problem constants: B=8, N=4096, C=1024, H=16, dh=64
#define BB 8
#define NN 4096
#define CC 1024
#define HH 16
#define DH 64
#define M_ROWS (BB * NN)          // 32768
#define QKV_COLS (3 * CC)         // 3072

// ---------------- static scratch -------------------------------------------
__device__ __align__(128) __half g_Yh[(size_t)M_ROWS * QKV_COLS];  // qkv fp16
__device__ __align__(128) __half g_Zh[(size_t)M_ROWS * CC];        // attn@v fp16
__device__ __align__(128) __half g_attnh[(size_t)BB * HH * DH * DH]; // attn fp16 [bh][d][e]
__device__ __align__(128) float g_sspart[(size_t)(M_ROWS / 128) * 2048];
__device__ __align__(128) __half g_Af16[(size_t)M_ROWS * CC];      // x fp16 [M,K]
__device__ __align__(128) __half g_Wf16[(size_t)QKV_COLS * CC];    // W^T fp16 [N,K]

// ============================ helpers =======================================
__device__ __forceinline__ uint32_t smem_u32(const void* p) {
  uint32_t a;
  asm("{ .reg .u64 t; cvta.to.shared.u64 t, %1; cvt.u32.u64 %0, t; }" : "=r"(a) : "l"(p));
  return a;
}
__device__ __forceinline__ void cp_async16(uint32_t dst, const void* src) {
  asm volatile("cp.async.cg.shared.global [%0], [%1], 16;" :: "r"(dst), "l"(src));
}
__device__ __forceinline__ void ldsm_x4(uint32_t* r, uint32_t addr) {
  asm volatile("ldmatrix.sync.aligned.m8n8.x4.shared.b16 {%0,%1,%2,%3}, [%4];"
               : "=r"(r[0]), "=r"(r[1]), "=r"(r[2]), "=r"(r[3]) : "r"(addr));
}
__device__ __forceinline__ void ldsm_x4_t(uint32_t* r, uint32_t addr) {
  asm volatile("ldmatrix.sync.aligned.m8n8.x4.trans.shared.b16 {%0,%1,%2,%3}, [%4];"
               : "=r"(r[0]), "=r"(r[1]), "=r"(r[2]), "=r"(r[3]) : "r"(addr));
}
__device__ __forceinline__ void ldsm_x2(uint32_t* r, uint32_t addr) {
  asm volatile("ldmatrix.sync.aligned.m8n8.x2.shared.b16 {%0,%1}, [%2];"
               : "=r"(r[0]), "=r"(r[1]) : "r"(addr));
}
__device__ __forceinline__ void mma_f16(float* c, const uint32_t* a, uint32_t b0,
                                        uint32_t b1) {
  asm volatile(
      "mma.sync.aligned.m16n8k16.row.col.f32.f16.f16.f32 "
      "{%0,%1,%2,%3}, {%4,%5,%6,%7}, {%8,%9}, {%0,%1,%2,%3};"
      : "+f"(c[0]), "+f"(c[1]), "+f"(c[2]), "+f"(c[3])
      : "r"(a[0]), "r"(a[1]), "r"(a[2]), "r"(a[3]), "r"(b0), "r"(b1));
}

// ---------------------------------------------------------------------------
// fp16 tensor-core GEMM (measured-best config, unchanged).
// ---------------------------------------------------------------------------
#define HSTAGE 32768                     // A 16KB + B 16KB
#define HGEMM_SMEM (3 * HSTAGE)          // 96KB

template <int OUT_HALF, int SUMSQ>
__global__ __launch_bounds__(256, 2) void hgemm(
    const __half* __restrict__ A, const __half* __restrict__ Bt,
    void* __restrict__ Cv, const float* __restrict__ bias, int N, int K) {
  extern __shared__ char smembuf[];
  const uint32_t sbase = smem_u32(smembuf);
  const int tid = threadIdx.x, lane = tid & 31, wid = tid >> 5;
  const int wm = wid & 1, wn = wid >> 1;   // 2 x 4 warp grid
  const size_t bm = (size_t)blockIdx.y * 128;
  const size_t bn = (size_t)blockIdx.x * 128;

  float acc[4][4][4];
#pragma unroll
  for (int mi = 0; mi < 4; ++mi)
#pragma unroll
    for (int nj = 0; nj < 4; ++nj)
#pragma unroll
      for (int j = 0; j < 4; ++j) acc[mi][nj][j] = 0.0f;

  auto issue_loads = [&](int kt, int st) {
    const uint32_t sA = sbase + st * HSTAGE;
    const uint32_t sB = sA + 16384;
    const __half* Ag = A + bm * K + kt * 64;
    const __half* Bg = Bt + bn * K + kt * 64;
#pragma unroll
    for (int i = 0; i < 4; ++i) {
      int idx = tid + i * 256;
      int r = idx >> 3, g = idx & 7;
      cp_async16(sA + r * 128 + ((g ^ (r & 7)) << 4), Ag + (size_t)r * K + g * 8);
    }
#pragma unroll
    for (int i = 0; i < 4; ++i) {
      int idx = tid + i * 256;
      int r = idx >> 3, g = idx & 7;
      cp_async16(sB + r * 128 + ((g ^ (r & 7)) << 4), Bg + (size_t)r * K + g * 8);
    }
    asm volatile("cp.async.commit_group;");
  };

  const int nt = K >> 6;
  issue_loads(0, 0);
  if (nt > 1) issue_loads(1, 1);

  const int hi8 = (lane >> 4) & 1;
  const int rsel = lane & 15;

  for (int kt = 0; kt < nt; ++kt) {
    if (kt + 1 < nt) {
      asm volatile("cp.async.wait_group 1;");
    } else {
      asm volatile("cp.async.wait_group 0;");
    }
    __syncthreads();
    if (kt + 2 < nt) issue_loads(kt + 2, (kt + 2) % 3);

    const int st = kt % 3;
    const uint32_t sA = sbase + st * HSTAGE;
    const uint32_t sB = sA + 16384;
#pragma unroll
    for (int ks = 0; ks < 4; ++ks) {
      const int g16 = 2 * ks + hi8;
      uint32_t a[4][4], b[2][4];
#pragma unroll
      for (int mi = 0; mi < 4; ++mi) {
        int mrow = wm * 64 + mi * 16 + rsel;
        ldsm_x4(a[mi], sA + mrow * 128 + ((g16 ^ (mrow & 7)) << 4));
      }
#pragma unroll
      for (int nb = 0; nb < 2; ++nb) {
        int nrow = wn * 32 + nb * 16 + rsel;
        ldsm_x4(b[nb], sB + nrow * 128 + ((g16 ^ (nrow & 7)) << 4));
      }
#pragma unroll
      for (int mi = 0; mi < 4; ++mi)
#pragma unroll
        for (int nj = 0; nj < 4; ++nj)
          mma_f16(acc[mi][nj], a[mi], b[nj >> 1][nj & 1], b[nj >> 1][(nj & 1) + 2]);
    }
  }

  const int rr = lane >> 2, cc2 = (lane & 3) * 2;
#pragma unroll
  for (int mi = 0; mi < 4; ++mi) {
    size_t row = bm + wm * 64 + mi * 16 + rr;
#pragma unroll
    for (int nj = 0; nj < 4; ++nj) {
      size_t col = bn + wn * 32 + nj * 8 + cc2;
      if (OUT_HALF) {
        __half* C = (__half*)Cv;
        *(__half2*)(C + row * N + col) =
            __floats2half2_rn(acc[mi][nj][0], acc[mi][nj][1]);
        *(__half2*)(C + (row + 8) * N + col) =
            __floats2half2_rn(acc[mi][nj][2], acc[mi][nj][3]);
      } else {
        float* C = (float*)Cv;
        float b0 = 0.0f, b1 = 0.0f;
        if (bias) { b0 = bias[col]; b1 = bias[col + 1]; }
        *(float2*)(C + row * N + col) =
            make_float2(acc[mi][nj][0] + b0, acc[mi][nj][1] + b1);
        *(float2*)(C + (row + 8) * N + col) =
            make_float2(acc[mi][nj][2] + b0, acc[mi][nj][3] + b1);
      }
    }
  }

  if (SUMSQ) {
    if (bn < 2048) {
      __syncthreads();
      float* sq = (float*)smembuf;          // [128 cols][16 slots] = 8KB
      const int slot = wm * 8 + rr;
#pragma unroll
      for (int nj = 0; nj < 4; ++nj) {
        int c0 = wn * 32 + nj * 8 + cc2;
        float p0 = 0.0f, p1 = 0.0f;
#pragma unroll
        for (int mi = 0; mi < 4; ++mi) {
          p0 += acc[mi][nj][0] * acc[mi][nj][0] + acc[mi][nj][2] * acc[mi][nj][2];
          p1 += acc[mi][nj][1] * acc[mi][nj][1] + acc[mi][nj][3] * acc[mi][nj][3];
        }
        sq[c0 * 16 + slot] = p0;
        sq[(c0 + 1) * 16 + slot] = p1;
      }
      __syncthreads();
      if (tid < 128) {
        float s = 0.0f;
#pragma unroll
        for (int j = 0; j < 16; ++j) s += sq[tid * 16 + j];
        g_sspart[(size_t)blockIdx.y * 2048 + bn + tid] = s;
      }
    }
  }
}

// ---------------------------------------------------------------------------
__global__ __launch_bounds__(256) void f2h_kernel(const float* __restrict__ A,
                                                  __half* __restrict__ O) {
  size_t i = ((size_t)blockIdx.x * 256 + threadIdx.x) * 8;
  float4 v0 = *(const float4*)(A + i);
  float4 v1 = *(const float4*)(A + i + 4);
  union { __half2 h[4]; uint4 u; } o;
  o.h[0] = __floats2half2_rn(v0.x, v0.y);
  o.h[1] = __floats2half2_rn(v0.z, v0.w);
  o.h[2] = __floats2half2_rn(v1.x, v1.y);
  o.h[3] = __floats2half2_rn(v1.z, v1.w);
  *(uint4*)(O + i) = o.u;
}

// ---------------------------------------------------------------------------
__global__ __launch_bounds__(256) void wtrans_kernel(const float* __restrict__ W,
                                                     __half* __restrict__ O,
                                                     int K, int N) {
  __shared__ float s[32][33];
  const int n0 = blockIdx.x * 32, k0 = blockIdx.y * 32;
  const int tx = threadIdx.x & 31, tg = threadIdx.x >> 5;
#pragma unroll
  for (int j = 0; j < 4; ++j) {
    int kr = tg + j * 8;
    s[kr][tx] = W[(size_t)(k0 + kr) * N + n0 + tx];
  }
  __syncthreads();
#pragma unroll
  for (int j = 0; j < 4; ++j) {
    int nr = tg + j * 8;
    O[(size_t)(n0 + nr) * K + k0 + tx] = __float2half_rn(s[tx][nr]);
  }
}

// ---------------------------------------------------------------------------
// Fused gram + softmax per (b,h). Warp-per-k-slice decomposition: warp w
// accumulates the FULL 64x64 gram over tokens {chunk*128 + w*16 .. +15} for
// all 32 chunks (512 tokens/warp). Per chunk per warp: 4 A-ldsm + 4 B-ldsm
// for 32 MMAs (vs 40:32 before). Deterministic 3-phase cross-warp reduction
// in smem, then softmax with folded norms.
// ---------------------------------------------------------------------------
#define GRSM_STAGE 32768                 // q 16KB + k 16KB
#define GRSM_SMEM (3 * GRSM_STAGE)       // 96KB; 4x[64][68] fp32 bufs overlay

__global__ __launch_bounds__(256) void gramsm_kernel(const float* __restrict__ temp) {
  extern __shared__ char gsm[];
  __shared__ float nq[64], nk[64];
  const uint32_t sbase = smem_u32(gsm);
  const int bh = blockIdx.x, b = bh >> 4, h = bh & 15;
  const int tid = threadIdx.x, lane = tid & 31, wid = tid >> 5;
  const __half* Yq = g_Yh + (size_t)b * NN * QKV_COLS + h * DH;
  const __half* Yk = Yq + CC;

  float acc[4][8][4];                     // mi(d16) x nj(e8) x frag
#pragma unroll
  for (int mi = 0; mi < 4; ++mi)
#pragma unroll
    for (int nj = 0; nj < 8; ++nj)
#pragma unroll
      for (int j = 0; j < 4; ++j) acc[mi][nj][j] = 0.0f;

  auto issue_chunk = [&](int ch, int st) {
    const uint32_t qb = sbase + st * GRSM_STAGE;
    const uint32_t kb = qb + 16384;
#pragma unroll
    for (int i = 0; i < 4; ++i) {
      int idx = tid + i * 256;
      int r = idx >> 3, g = idx & 7;
      size_t go = (size_t)(ch * 128 + r) * QKV_COLS + g * 8;
      uint32_t so = r * 128 + ((g ^ (r & 7)) << 4);
      cp_async16(qb + so, Yq + go);
      cp_async16(kb + so, Yk + go);
    }
    asm volatile("cp.async.commit_group;");
  };

  issue_chunk(0, 0);
  issue_chunk(1, 1);

  // norms: reduce 32 per-Mtile partials (overlapped with first prefetches)
  if (tid < 64) {
    float sq = 0.0f, sk = 0.0f;
#pragma unroll
    for (int t = 0; t < 32; ++t) {
      const float* P = g_sspart + (size_t)(b * 32 + t) * 2048;
      sq += P[h * DH + tid];
      sk += P[CC + h * DH + tid];
    }
    nq[tid] = fmaxf(sqrtf(sq), 1e-12f);
    nk[tid] = fmaxf(sqrtf(sk), 1e-12f);
  }

  // A-side lane mapping (validated x4_t pattern), s = wid
  const int tokA = wid * 16 + (lane & 7) + ((lane >> 4) << 3);
  // B-side: lanes 0-15 granule 2ge, lanes 16-31 granule 2ge+1 (x4_t ext.)
  const int tokB = wid * 16 + (lane & 7) + (((lane >> 3) & 1) << 3);
  const int gsel = lane >> 4;             // 0 or 1

  for (int ch = 0; ch < 32; ++ch) {
    if (ch + 1 < 32) {
      asm volatile("cp.async.wait_group 1;");
    } else {
      asm volatile("cp.async.wait_group 0;");
    }
    __syncthreads();
    if (ch + 2 < 32) issue_chunk(ch + 2, (ch + 2) % 3);

    const uint32_t qb = sbase + (ch % 3) * GRSM_STAGE;
    const uint32_t kb = qb + 16384;

    uint32_t a[4][4];
#pragma unroll
    for (int mi = 0; mi < 4; ++mi) {
      int gd = mi * 2 + ((lane >> 3) & 1);
      ldsm_x4_t(a[mi], qb + tokA * 128 + ((gd ^ (tokA & 7)) << 4));
    }
#pragma unroll
    for (int ge = 0; ge < 4; ++ge) {
      uint32_t bx[4];
      int gg = ge * 2 + gsel;
      ldsm_x4_t(bx, kb + tokB * 128 + ((gg ^ (tokB & 7)) << 4));
#pragma unroll
      for (int mi = 0; mi < 4; ++mi) {
        mma_f16(acc[mi][2 * ge],     a[mi], bx[0], bx[1]);
        mma_f16(acc[mi][2 * ge + 1], a[mi], bx[2], bx[3]);
      }
    }
  }
  __syncthreads();                        // pipeline smem dead

  // 3-phase deterministic cross-warp reduction: 4 bufs of [64][68]
  float* buf = (float*)gsm;
  const int rr = lane >> 2, cc2 = (lane & 3) * 2;
  if (wid < 4) {
    float* Bf = buf + wid * (64 * 68);
#pragma unroll
    for (int mi = 0; mi < 4; ++mi)
#pragma unroll
      for (int nj = 0; nj < 8; ++nj) {
        int c0 = nj * 8 + cc2;
        Bf[(mi * 16 + rr) * 68 + c0]     = acc[mi][nj][0];
        Bf[(mi * 16 + rr) * 68 + c0 + 1] = acc[mi][nj][1];
        Bf[(mi * 16 + 8 + rr) * 68 + c0]     = acc[mi][nj][2];
        Bf[(mi * 16 + 8 + rr) * 68 + c0 + 1] = acc[mi][nj][3];
      }
  }
  __syncthreads();
  if (wid >= 4) {
    float* Bf = buf + (wid - 4) * (64 * 68);
#pragma unroll
    for (int mi = 0; mi < 4; ++mi)
#pragma unroll
      for (int nj = 0; nj < 8; ++nj) {
        int c0 = nj * 8 + cc2;
        Bf[(mi * 16 + rr) * 68 + c0]     += acc[mi][nj][0];
        Bf[(mi * 16 + rr) * 68 + c0 + 1] += acc[mi][nj][1];
        Bf[(mi * 16 + 8 + rr) * 68 + c0]     += acc[mi][nj][2];
        Bf[(mi * 16 + 8 + rr) * 68 + c0 + 1] += acc[mi][nj][3];
      }
  }
  __syncthreads();
  for (int i = tid; i < 64 * 64; i += 256) {
    int d = i >> 6, e = i & 63;
    float s = buf[d * 68 + e] + buf[4352 + d * 68 + e] +
              buf[2 * 4352 + d * 68 + e] + buf[3 * 4352 + d * 68 + e];
    buf[d * 68 + e] = s;
  }
  __syncthreads();

  if (tid < 64) {
    const int d = tid;
    const float sc = temp[h] / nq[d];
    float row[64];
    float m = -3.402823466e38f;
#pragma unroll
    for (int e = 0; e < 64; ++e) {
      row[e] = buf[d * 68 + e] * sc / nk[e];
      m = fmaxf(m, row[e]);
    }
    float sum = 0.0f;
#pragma unroll
    for (int e = 0; e < 64; ++e) {
      row[e] = expf(row[e] - m);
      sum += row[e];
    }
    const float inv = 1.0f / sum;
    __half2* Ao = (__half2*)(g_attnh + (size_t)bh * 4096 + d * 64);
#pragma unroll
    for (int e2 = 0; e2 < 32; ++e2)
      Ao[e2] = __floats2half2_rn(row[2 * e2] * inv, row[2 * e2 + 1] * inv);
  }
}

// ---------------------------------------------------------------------------
// Tensor-core attnv: Z[n][d] = sum_e v[n][e] attn[d][e]. (unchanged)
// ---------------------------------------------------------------------------
__global__ __launch_bounds__(256) void attnv_tc_kernel() {
  __shared__ __align__(16) __half vt[256 * 64];
  __shared__ __align__(16) __half at[64 * 64];
  const int bh = blockIdx.y, b = bh >> 4, h = bh & 15;
  const int tb = blockIdx.x * 256;
  const int tid = threadIdx.x, lane = tid & 31, wid = tid >> 5;
  const int wm = wid & 3, wd = wid >> 2;
  const uint32_t vb = smem_u32(vt), ab = smem_u32(at);

  const __half* Vg = g_Yh + (size_t)(b * NN + tb) * QKV_COLS + 2 * CC + h * DH;
#pragma unroll
  for (int i = 0; i < 8; ++i) {
    int idx = tid + i * 256;
    int r = idx >> 3, g = idx & 7;
    cp_async16(vb + r * 128 + ((g ^ (r & 7)) << 4), Vg + (size_t)r * QKV_COLS + g * 8);
  }
  const __half* Ag = g_attnh + (size_t)bh * 4096;
#pragma unroll
  for (int i = 0; i < 2; ++i) {
    int idx = tid + i * 256;
    int r = idx >> 3, g = idx & 7;
    cp_async16(ab + r * 128 + ((g ^ (r & 7)) << 4), Ag + r * 64 + g * 8);
  }
  asm volatile("cp.async.commit_group;");
  asm volatile("cp.async.wait_group 0;");
  __syncthreads();

  float acc[4][4][4] = {};
#pragma unroll
  for (int ks = 0; ks < 4; ++ks) {
    const int ge0 = ks * 2;
    uint32_t a[4][4], bf[4][2];
#pragma unroll
    for (int mi = 0; mi < 4; ++mi) {
      int tok = wm * 64 + mi * 16 + (lane & 7) + (((lane >> 3) & 1) << 3);
      int gg = ge0 + (lane >> 4);
      ldsm_x4(a[mi], vb + tok * 128 + ((gg ^ (tok & 7)) << 4));
    }
#pragma unroll
    for (int dj = 0; dj < 4; ++dj) {
      int d = wd * 32 + dj * 8 + (lane & 7);
      int gg = ge0 + ((lane >> 3) & 1);
      ldsm_x2(bf[dj], ab + d * 128 + ((gg ^ (d & 7)) << 4));
    }
#pragma unroll
    for (int mi = 0; mi < 4; ++mi)
#pragma unroll
      for (int dj = 0; dj < 4; ++dj)
        mma_f16(acc[mi][dj], a[mi], bf[dj][0], bf[dj][1]);
  }

  const int rr = lane >> 2, cc2 = (lane & 3) * 2;
#pragma unroll
  for (int mi = 0; mi < 4; ++mi) {
    size_t tok = (size_t)(b * NN + tb + wm * 64 + mi * 16 + rr);
#pragma unroll
    for (int dj = 0; dj < 4; ++dj) {
      size_t col = h * DH + wd * 32 + dj * 8 + cc2;
      *(__half2*)(g_Zh + tok * CC + col) =
          __floats2half2_rn(acc[mi][dj][0], acc[mi][dj][1]);
      *(__half2*)(g_Zh + (tok + 8) * CC + col) =
          __floats2half2_rn(acc[mi][dj][2], acc[mi][dj][3]);
    }
  }
}

// ---------------------------------------------------------------------------
extern "C" void kernel_launch(void* const* d_in, const int* in_sizes, int n_in,
                              void* d_out, int out_size) {
  const float* x      = (const float*)d_in[0];
  const float* w_qkv  = (const float*)d_in[1];
  const float* temp   = (const float*)d_in[2];
  const float* w_proj = (const float*)d_in[3];
  const float* b_proj = (const float*)d_in[4];
  float* out = (float*)d_out;

  static __half *Yh = nullptr, *Ah = nullptr, *Wh = nullptr, *Zh = nullptr;
  if (Yh == nullptr) {
    cudaGetSymbolAddress((void**)&Yh, g_Yh);
    cudaGetSymbolAddress((void**)&Zh, g_Zh);
    cudaGetSymbolAddress((void**)&Ah, g_Af16);
    cudaGetSymbolAddress((void**)&Wh, g_Wf16);
    cudaFuncSetAttribute((const void*)hgemm<1, 1>,
                         cudaFuncAttributeMaxDynamicSharedMemorySize, HGEMM_SMEM);
    cudaFuncSetAttribute((const void*)hgemm<0, 0>,
                         cudaFuncAttributeMaxDynamicSharedMemorySize, HGEMM_SMEM);
    cudaFuncSetAttribute((const void*)gramsm_kernel,
                         cudaFuncAttributeMaxDynamicSharedMemorySize, GRSM_SMEM);
  }

  // prep
  f2h_kernel<<<(size_t)M_ROWS * CC / 2048, 256>>>(x, Ah);
  wtrans_kernel<<<dim3(QKV_COLS / 32, CC / 32), 256>>>(w_qkv, Wh, CC, QKV_COLS);

  // K1: qkv = x @ w_qkv -> fp16 Yh, + sumsq partials
  hgemm<1, 1><<<dim3(QKV_COLS / 128, M_ROWS / 128), 256, HGEMM_SMEM>>>(
      Ah, Wh, Yh, nullptr, QKV_COLS, CC);

  gramsm_kernel<<<BB * HH, 256, GRSM_SMEM>>>(temp);
  attnv_tc_kernel<<<dim3(NN / 256, BB * HH), 256>>>();

  // K5
  wtrans_kernel<<<dim3(CC / 32, CC / 32), 256>>>(w_proj, Wh, CC, CC);
  hgemm<0, 0><<<dim3(CC / 128, M_ROWS / 128), 256, HGEMM_SMEM>>>(
      Zh, Wh, out, b_proj, CC, CC);
}